// round 1
// baseline (speedup 1.0000x reference)
#include <cuda_runtime.h>
#include <cuda_bf16.h>

#define DD   256
#define NTOK 32768
#define KCB  8192

#define BM 128
#define BN 64
#define BK 32
#define TM 8
#define TN 4
#define BS_STRIDE (BN + 4)   // pad so Bs[kk][tx*4] is 16B-aligned and conflicts are mild

__device__ float g_esq[KCB];
__device__ int   g_idx[NTOK];

// ---------------------------------------------------------------------------
// ||e_k||^2 per codebook row, warp per row
// ---------------------------------------------------------------------------
__global__ void esq_kernel(const float* __restrict__ E) {
    int k    = blockIdx.x * 8 + (threadIdx.x >> 5);
    int lane = threadIdx.x & 31;
    const float* row = E + (size_t)k * DD;
    float s = 0.f;
#pragma unroll
    for (int d = lane; d < DD; d += 32) { float v = row[d]; s = fmaf(v, v, s); }
#pragma unroll
    for (int o = 16; o; o >>= 1) s += __shfl_xor_sync(0xffffffffu, s, o);
    if (lane == 0) g_esq[k] = s;
}

// ---------------------------------------------------------------------------
// Main: tiled GEMM (tokens x codes over D) with running argmin epilogue.
// score = ||e||^2 - 2 * <z, e>   (||z||^2 constant per token -> dropped)
// ---------------------------------------------------------------------------
__global__ __launch_bounds__(256, 2) void argmin_kernel(
    const float* __restrict__ z,   // (D, N): z[d*N + n]
    const float* __restrict__ E)   // (K, D): E[k*D + d]
{
    __shared__ float As[BK][BM];          // [d_local][token]
    __shared__ float Bs[BK][BS_STRIDE];   // [d_local][code]
    __shared__ float sEsq[BN];
    __shared__ float sBest[BM][16];
    __shared__ int   sBIdx[BM][16];

    const int tid = threadIdx.x;
    const int tx  = tid & 15;    // code group  (16)
    const int ty  = tid >> 4;    // token group (16)
    const int n0  = blockIdx.x * BM;

    float best[TM];
    int   bidx[TM];
#pragma unroll
    for (int i = 0; i < TM; i++) { best[i] = 3.4e38f; bidx[i] = 0; }

    for (int kc = 0; kc < KCB; kc += BN) {
        __syncthreads();                     // protect sEsq vs previous epilogue reads
        if (tid < BN) sEsq[tid] = g_esq[kc + tid];

        float acc[TM][TN];
#pragma unroll
        for (int i = 0; i < TM; i++)
#pragma unroll
            for (int j = 0; j < TN; j++) acc[i][j] = 0.f;

        for (int d0 = 0; d0 < DD; d0 += BK) {
            __syncthreads();
            // load z tile: 128 tokens x 32 d  (coalesced over tokens)
#pragma unroll
            for (int it = 0; it < (BM * BK) / 256; it++) {
                int idx = tid + it * 256;
                int i = idx & (BM - 1);
                int j = idx >> 7;
                As[j][i] = z[(size_t)(d0 + j) * NTOK + n0 + i];
            }
            // load E tile: 64 codes x 32 d  (coalesced over d)
#pragma unroll
            for (int it = 0; it < (BN * BK) / 256; it++) {
                int idx = tid + it * 256;
                int jd = idx & 31;
                int jc = idx >> 5;
                Bs[jd][jc] = E[(size_t)(kc + jc) * DD + d0 + jd];
            }
            __syncthreads();
#pragma unroll
            for (int kk = 0; kk < BK; kk++) {
                float a[TM], b[TN];
#pragma unroll
                for (int i = 0; i < TM; i++) a[i] = As[kk][ty * TM + i];
#pragma unroll
                for (int j = 0; j < TN; j++) b[j] = Bs[kk][tx * TN + j];
#pragma unroll
                for (int i = 0; i < TM; i++)
#pragma unroll
                    for (int j = 0; j < TN; j++)
                        acc[i][j] = fmaf(a[i], b[j], acc[i][j]);
            }
        }

        // argmin epilogue for this 64-code chunk (strict < keeps smallest k on ties)
#pragma unroll
        for (int j = 0; j < TN; j++) {
            int   k = kc + tx * TN + j;
            float e = sEsq[tx * TN + j];
#pragma unroll
            for (int i = 0; i < TM; i++) {
                float s = fmaf(-2.f, acc[i][j], e);
                if (s < best[i]) { best[i] = s; bidx[i] = k; }
            }
        }
    }

    __syncthreads();
#pragma unroll
    for (int i = 0; i < TM; i++) {
        sBest[ty * TM + i][tx] = best[i];
        sBIdx[ty * TM + i][tx] = bidx[i];
    }
    __syncthreads();
    if (tid < BM) {
        float bs = sBest[tid][0];
        int   bi = sBIdx[tid][0];
#pragma unroll
        for (int t = 1; t < 16; t++) {
            float s = sBest[tid][t];
            int   x = sBIdx[tid][t];
            if (s < bs || (s == bs && x < bi)) { bs = s; bi = x; }
        }
        g_idx[n0 + tid] = bi;
    }
}

// ---------------------------------------------------------------------------
// Gather z_q[d][n] = E[idx[n]][d], transposed through smem for coalescing.
// ---------------------------------------------------------------------------
__global__ void gather_kernel(const float* __restrict__ E, float* __restrict__ out) {
    __shared__ float tile[32][DD + 1];
    const int n0   = blockIdx.x * 32;
    const int tid  = threadIdx.x;
    const int warp = tid >> 5, lane = tid & 31;
#pragma unroll
    for (int r = 0; r < 4; r++) {
        int tk = warp * 4 + r;
        int k  = g_idx[n0 + tk];
        const float* row = E + (size_t)k * DD;
#pragma unroll
        for (int d = lane; d < DD; d += 32) tile[tk][d] = row[d];
    }
    __syncthreads();
    for (int idx = tid; idx < 32 * DD; idx += 256) {
        int d  = idx >> 5;
        int nl = idx & 31;
        out[(size_t)d * NTOK + n0 + nl] = tile[nl][d];
    }
}

__global__ void write_idx_kernel(float* __restrict__ out) {
    int n = blockIdx.x * 256 + threadIdx.x;
    out[(size_t)DD * NTOK + n] = (float)g_idx[n];
}

// ---------------------------------------------------------------------------
extern "C" void kernel_launch(void* const* d_in, const int* in_sizes, int n_in,
                              void* d_out, int out_size) {
    const float* z = (const float*)d_in[0];   // z_e: (D, N)
    const float* E = (const float*)d_in[1];   // embeddings: (K, D)
    float* out = (float*)d_out;

    esq_kernel<<<KCB / 8, 256>>>(E);
    argmin_kernel<<<NTOK / BM, 256>>>(z, E);
    gather_kernel<<<NTOK / 32, 256>>>(E, out);
    if (out_size >= DD * NTOK + NTOK)
        write_idx_kernel<<<NTOK / 256, 256>>>(out);
}

// round 7
// speedup vs baseline: 1.9386x; 1.9386x over previous
#include <cuda_runtime.h>
#include <cuda_bf16.h>
#include <cstdint>

#define DD   256
#define NTOK 32768
#define KCB  8192

#define BM 64           // tokens per block
#define BN 128          // codes per chunk
#define BKD 32          // d per B tile
#define AS  264         // A smem row stride (elems), 528B, 16B-aligned rows
#define BSs 40          // B smem row stride (elems), 80B, 16B-aligned rows
#define TAU 0.05f

__device__ float          g_esq[KCB];
__device__ int            g_idx[NTOK];
__device__ __nv_bfloat16  g_Ehi[KCB * DD];
__device__ __nv_bfloat16  g_Elo[KCB * DD];
__device__ __nv_bfloat16  g_zhi[(size_t)NTOK * DD];
__device__ __nv_bfloat16  g_zlo[(size_t)NTOK * DD];
__device__ int            g_flag[NTOK];
__device__ unsigned long long g_best[NTOK];
__device__ int            g_nflag;

// ---------------------------------------------------------------------------
__global__ void esq_kernel(const float* __restrict__ E) {
    if (blockIdx.x == 0 && threadIdx.x == 0) g_nflag = 0;
    int k    = blockIdx.x * 8 + (threadIdx.x >> 5);
    int lane = threadIdx.x & 31;
    const float* row = E + (size_t)k * DD;
    float s = 0.f;
#pragma unroll
    for (int d = lane; d < DD; d += 32) { float v = row[d]; s = fmaf(v, v, s); }
#pragma unroll
    for (int o = 16; o; o >>= 1) s += __shfl_xor_sync(0xffffffffu, s, o);
    if (lane == 0) g_esq[k] = s;
}

__global__ void splitE_kernel(const float* __restrict__ E) {
    int i = blockIdx.x * 256 + threadIdx.x;
    float v = E[i];
    __nv_bfloat16 hi = __float2bfloat16(v);
    __nv_bfloat16 lo = __float2bfloat16(v - __bfloat162float(hi));
    g_Ehi[i] = hi; g_Elo[i] = lo;
}

// Transpose z (D,N) -> (N,D), split into bf16 hi/lo
__global__ void splitZ_kernel(const float* __restrict__ z) {
    __shared__ float t[32][33];
    int bx = blockIdx.x, by = blockIdx.y;
    int tx = threadIdx.x, ty = threadIdx.y;
    int n = bx * 32 + tx;
#pragma unroll
    for (int i = 0; i < 4; i++) {
        int d = by * 32 + ty + i * 8;
        t[ty + i * 8][tx] = z[(size_t)d * NTOK + n];
    }
    __syncthreads();
    int d2 = by * 32 + tx;
#pragma unroll
    for (int i = 0; i < 4; i++) {
        int n2 = bx * 32 + ty + i * 8;
        float v = t[tx][ty + i * 8];
        __nv_bfloat16 hi = __float2bfloat16(v);
        __nv_bfloat16 lo = __float2bfloat16(v - __bfloat162float(hi));
        g_zhi[(size_t)n2 * DD + d2] = hi;
        g_zlo[(size_t)n2 * DD + d2] = lo;
    }
}

// ---------------------------------------------------------------------------
__device__ __forceinline__ void mma_bf16(float c[4], const uint32_t a[4], const uint32_t b[2]) {
    asm volatile(
        "mma.sync.aligned.m16n8k16.row.col.f32.bf16.bf16.f32 "
        "{%0,%1,%2,%3}, {%4,%5,%6,%7}, {%8,%9}, {%0,%1,%2,%3};\n"
        : "+f"(c[0]), "+f"(c[1]), "+f"(c[2]), "+f"(c[3])
        : "r"(a[0]), "r"(a[1]), "r"(a[2]), "r"(a[3]), "r"(b[0]), "r"(b[1]));
}

__device__ __forceinline__ void merge3(float& b1, int& i1, float& b2, float v, int i) {
    if (v < b1) { b2 = b1; b1 = v; i1 = i; }
    else if (v < b2) { b2 = v; }
}
__device__ __forceinline__ void merge3t(float& b1, int& i1, float& b2,
                                        float B1, int I1, float B2) {
    if (B1 < b1) { b2 = fminf(b1, B2); b1 = B1; i1 = I1; }
    else         { b2 = fminf(b2, B1); }
}

__global__ __launch_bounds__(256, 2) void argmin_mma_kernel() {
    extern __shared__ char smem[];
    __nv_bfloat16* As_hi = (__nv_bfloat16*)smem;
    __nv_bfloat16* As_lo = As_hi + BM * AS;
    __nv_bfloat16* Bs_hi = As_lo + BM * AS;
    __nv_bfloat16* Bs_lo = Bs_hi + BN * BSs;
    float* sB1  = (float*)(Bs_lo + BN * BSs);
    int*   sI1  = (int*)  (sB1 + 4 * BM);
    float* sB2  = (float*)(sI1 + 4 * BM);
    float* rB1  = sB2 + 4 * BM;
    int*   rI1  = (int*)(rB1 + BM);
    float* rB2  = (float*)(rI1 + BM);
    float* sEsq = rB2 + BM;

    const int tid  = threadIdx.x;
    const int lane = tid & 31;
    const int wid  = tid >> 5;
    const int warpRow = wid >> 2;     // 2 row groups x 32 tokens
    const int warpCol = wid & 3;      // 4 col groups x 32 codes
    const int n0 = blockIdx.x * BM;

    // Load the 64-token A panel (full D, hi+lo) once.
#pragma unroll
    for (int it = 0; it < 8; it++) {
        int idx = tid + it * 256;
        int r = idx >> 5, seg = idx & 31;
        const uint4* sh = (const uint4*)(g_zhi + (size_t)(n0 + r) * DD) + seg;
        const uint4* sl = (const uint4*)(g_zlo + (size_t)(n0 + r) * DD) + seg;
        *(uint4*)(As_hi + r * AS + seg * 8) = *sh;
        *(uint4*)(As_lo + r * AS + seg * 8) = *sl;
    }
    if (tid < BM) { rB1[tid] = 3.4e38f; rB2[tid] = 3.4e38f; rI1[tid] = 0; }

    for (int kc = 0; kc < KCB; kc += BN) {
        if (tid < BN) sEsq[tid] = g_esq[kc + tid];

        float acc[2][4][4];
#pragma unroll
        for (int mi = 0; mi < 2; mi++)
#pragma unroll
            for (int ni = 0; ni < 4; ni++)
#pragma unroll
                for (int e = 0; e < 4; e++) acc[mi][ni][e] = 0.f;

        for (int d0 = 0; d0 < DD; d0 += BKD) {
            __syncthreads();
#pragma unroll
            for (int it = 0; it < 2; it++) {
                int idx = tid + it * 256;
                int c = idx >> 2, seg = idx & 3;
                const uint4* sh = (const uint4*)(g_Ehi + (size_t)(kc + c) * DD + d0) + seg;
                const uint4* sl = (const uint4*)(g_Elo + (size_t)(kc + c) * DD + d0) + seg;
                *(uint4*)(Bs_hi + c * BSs + seg * 8) = *sh;
                *(uint4*)(Bs_lo + c * BSs + seg * 8) = *sl;
            }
            __syncthreads();
#pragma unroll
            for (int ks = 0; ks < 2; ks++) {
                const int kofA = d0 + ks * 16 + (lane & 3) * 2;
                uint32_t ah[2][4], al[2][4];
#pragma unroll
                for (int mi = 0; mi < 2; mi++) {
                    int row = warpRow * 32 + mi * 16 + (lane >> 2);
                    ah[mi][0] = *(const uint32_t*)(As_hi + row * AS + kofA);
                    ah[mi][1] = *(const uint32_t*)(As_hi + (row + 8) * AS + kofA);
                    ah[mi][2] = *(const uint32_t*)(As_hi + row * AS + kofA + 8);
                    ah[mi][3] = *(const uint32_t*)(As_hi + (row + 8) * AS + kofA + 8);
                    al[mi][0] = *(const uint32_t*)(As_lo + row * AS + kofA);
                    al[mi][1] = *(const uint32_t*)(As_lo + (row + 8) * AS + kofA);
                    al[mi][2] = *(const uint32_t*)(As_lo + row * AS + kofA + 8);
                    al[mi][3] = *(const uint32_t*)(As_lo + (row + 8) * AS + kofA + 8);
                }
                const int kofB = ks * 16 + (lane & 3) * 2;
                uint32_t bh[4][2], bl[4][2];
#pragma unroll
                for (int ni = 0; ni < 4; ni++) {
                    int c = warpCol * 32 + ni * 8 + (lane >> 2);
                    bh[ni][0] = *(const uint32_t*)(Bs_hi + c * BSs + kofB);
                    bh[ni][1] = *(const uint32_t*)(Bs_hi + c * BSs + kofB + 8);
                    bl[ni][0] = *(const uint32_t*)(Bs_lo + c * BSs + kofB);
                    bl[ni][1] = *(const uint32_t*)(Bs_lo + c * BSs + kofB + 8);
                }
#pragma unroll
                for (int mi = 0; mi < 2; mi++)
#pragma unroll
                    for (int ni = 0; ni < 4; ni++) {
                        mma_bf16(acc[mi][ni], ah[mi], bh[ni]);   // hi*hi
                        mma_bf16(acc[mi][ni], ah[mi], bl[ni]);   // hi*lo
                        mma_bf16(acc[mi][ni], al[mi], bh[ni]);   // lo*hi
                    }
            }
        }
        __syncthreads();

        // epilogue: per-thread top-2 for its 4 token rows over this 128-code chunk
        float tb1[4], tb2[4]; int ti1[4];
#pragma unroll
        for (int r = 0; r < 4; r++) { tb1[r] = 3.4e38f; tb2[r] = 3.4e38f; ti1[r] = 0; }
#pragma unroll
        for (int mi = 0; mi < 2; mi++)
#pragma unroll
            for (int h = 0; h < 2; h++) {
                int ridx = mi * 2 + h;
#pragma unroll
                for (int ni = 0; ni < 4; ni++)
#pragma unroll
                    for (int e2 = 0; e2 < 2; e2++) {
                        int colL = warpCol * 32 + ni * 8 + (lane & 3) * 2 + e2;
                        float v = fmaf(-2.f, acc[mi][ni][h * 2 + e2], sEsq[colL]);
                        merge3(tb1[ridx], ti1[ridx], tb2[ridx], v, kc + colL);
                    }
            }
        // reduce across the 4 threads of each quad (columns)
#pragma unroll
        for (int off = 1; off <= 2; off <<= 1)
#pragma unroll
            for (int r = 0; r < 4; r++) {
                float B1 = __shfl_xor_sync(0xffffffffu, tb1[r], off);
                int   I1 = __shfl_xor_sync(0xffffffffu, ti1[r], off);
                float B2 = __shfl_xor_sync(0xffffffffu, tb2[r], off);
                merge3t(tb1[r], ti1[r], tb2[r], B1, I1, B2);
            }
        if ((lane & 3) == 0) {
#pragma unroll
            for (int mi = 0; mi < 2; mi++)
#pragma unroll
                for (int h = 0; h < 2; h++) {
                    int row = warpRow * 32 + mi * 16 + (lane >> 2) + h * 8;
                    int r = mi * 2 + h;
                    sB1[warpCol * BM + row] = tb1[r];
                    sI1[warpCol * BM + row] = ti1[r];
                    sB2[warpCol * BM + row] = tb2[r];
                }
        }
        __syncthreads();
        if (tid < BM) {
            float b1 = rB1[tid], b2 = rB2[tid]; int i1 = rI1[tid];
#pragma unroll
            for (int w = 0; w < 4; w++)
                merge3t(b1, i1, b2, sB1[w * BM + tid], sI1[w * BM + tid], sB2[w * BM + tid]);
            rB1[tid] = b1; rI1[tid] = i1; rB2[tid] = b2;
        }
        __syncthreads();
    }

    if (tid < BM) {
        int n = n0 + tid;
        g_idx[n] = rI1[tid];
        if (rB2[tid] - rB1[tid] <= TAU) {          // ambiguous -> exact rescue
            g_best[n] = ~0ull;
            int p = atomicAdd(&g_nflag, 1);
            g_flag[p] = n;
        }
    }
}

// ---------------------------------------------------------------------------
__device__ __forceinline__ unsigned int ord_f32(float v) {
    unsigned int s = __float_as_uint(v);
    return (s & 0x80000000u) ? ~s : (s | 0x80000000u);
}

// Exact fp32 re-scoring of flagged tokens over all K codes.
__global__ void rescue_kernel(const float* __restrict__ z, const float* __restrict__ E) {
    __shared__ float zc[4][260];
    __shared__ unsigned long long sk[4][64];
    __shared__ int stok[4];
    const int cnt = g_nflag;
    if (cnt == 0) return;
    const int nbat = (cnt + 3) >> 2;
    const int items = nbat * 8;
    const int tid = threadIdx.x;
    const int t  = tid & 3;
    const int c0 = tid >> 2;

    for (int wi = blockIdx.x; wi < items; wi += gridDim.x) {
        int bat = wi >> 3, split = wi & 7;
        __syncthreads();
        int fi = bat * 4 + t; if (fi >= cnt) fi = cnt - 1;
        int n = g_flag[fi];
        if (c0 == 0) stok[t] = n;
        for (int d = c0; d < DD; d += 64) zc[t][d] = z[(size_t)d * NTOK + n];
        __syncthreads();

        unsigned long long key = ~0ull;
#pragma unroll 1
        for (int j = 0; j < 16; j++) {
            int c = split * 1024 + c0 + 64 * j;
            const float4* er = (const float4*)(E + (size_t)c * DD);
            float s = 0.f;
#pragma unroll
            for (int d4 = 0; d4 < DD / 4; d4++) {
                float4 e = er[d4];
                s = fmaf(e.x, zc[t][d4 * 4 + 0], s);
                s = fmaf(e.y, zc[t][d4 * 4 + 1], s);
                s = fmaf(e.z, zc[t][d4 * 4 + 2], s);
                s = fmaf(e.w, zc[t][d4 * 4 + 3], s);
            }
            float dist = fmaf(-2.f, s, g_esq[c]);
            unsigned long long k = ((unsigned long long)ord_f32(dist) << 13) | (unsigned)c;
            key = min(key, k);
        }
        sk[t][c0] = key;
        __syncthreads();
        if (tid < 4) {
            unsigned long long m = sk[tid][0];
            for (int i = 1; i < 64; i++) m = min(m, sk[tid][i]);
            atomicMin(&g_best[stok[tid]], m);
        }
        __syncthreads();
    }
}

__global__ void rescue_fix_kernel() {
    int cnt = g_nflag;
    int i = blockIdx.x * 256 + threadIdx.x;
    if (i < cnt) {
        int n = g_flag[i];
        g_idx[n] = (int)(g_best[n] & 0x1FFFull);
    }
}

// ---------------------------------------------------------------------------
__global__ void gather_kernel(const float* __restrict__ E, float* __restrict__ out) {
    __shared__ float tile[32][DD + 1];
    const int n0   = blockIdx.x * 32;
    const int tid  = threadIdx.x;
    const int warp = tid >> 5, lane = tid & 31;
#pragma unroll
    for (int r = 0; r < 4; r++) {
        int tk = warp * 4 + r;
        int k  = g_idx[n0 + tk];
        const float* row = E + (size_t)k * DD;
#pragma unroll
        for (int d = lane; d < DD; d += 32) tile[tk][d] = row[d];
    }
    __syncthreads();
    for (int idx = tid; idx < 32 * DD; idx += 256) {
        int d  = idx >> 5;
        int nl = idx & 31;
        out[(size_t)d * NTOK + n0 + nl] = tile[nl][d];
    }
}

__global__ void write_idx_kernel(float* __restrict__ out) {
    int n = blockIdx.x * 256 + threadIdx.x;
    out[(size_t)DD * NTOK + n] = (float)g_idx[n];
}

// ---------------------------------------------------------------------------
extern "C" void kernel_launch(void* const* d_in, const int* in_sizes, int n_in,
                              void* d_out, int out_size) {
    const float* z = (const float*)d_in[0];   // (D, N)
    const float* E = (const float*)d_in[1];   // (K, D)
    float* out = (float*)d_out;

    const int SMEM = (2 * BM * AS + 2 * BN * BSs) * 2
                   + 3 * 4 * BM * 4 + 3 * BM * 4 + BN * 4;
    cudaFuncSetAttribute(argmin_mma_kernel,
                         cudaFuncAttributeMaxDynamicSharedMemorySize, SMEM);

    esq_kernel   <<<KCB / 8, 256>>>(E);
    splitE_kernel<<<KCB * DD / 256, 256>>>(E);
    {
        dim3 b(32, 8), g(NTOK / 32, DD / 32);
        splitZ_kernel<<<g, b>>>(z);
    }
    argmin_mma_kernel<<<NTOK / BM, 256, SMEM>>>();
    rescue_kernel<<<256, 256>>>(z, E);
    rescue_fix_kernel<<<NTOK / 256, 256>>>();
    gather_kernel<<<NTOK / 32, 256>>>(E, out);
    if (out_size >= DD * NTOK + NTOK)
        write_idx_kernel<<<NTOK / 256, 256>>>(out);
}

// round 8
// speedup vs baseline: 2.4217x; 1.2492x over previous
#include <cuda_runtime.h>
#include <cuda_bf16.h>
#include <cstdint>

#define DD   256
#define NTOK 32768
#define KCB  8192

#define BM 64           // tokens per block
#define BN 128          // codes per chunk
#define BKD 32          // d per B tile
#define AS  264         // A smem row stride (elems); 528B rows -> conflict-free LDSM
#define BSs 40          // B smem row stride (elems); 80B rows  -> conflict-free LDSM
#define BUFE (BN * BSs) // elems per precision per B buffer (5120)
#define NTILE ((KCB / BN) * (DD / BKD))   // 512
#define TAU 0.05f

__device__ float          g_esq[KCB];
__device__ int            g_idx[NTOK];
__device__ __nv_bfloat16  g_Ehi[KCB * DD];
__device__ __nv_bfloat16  g_Elo[KCB * DD];
__device__ __nv_bfloat16  g_zhi[(size_t)NTOK * DD];
__device__ __nv_bfloat16  g_zlo[(size_t)NTOK * DD];
__device__ int            g_flag[NTOK];
__device__ unsigned long long g_best[NTOK];
__device__ int            g_nflag;

// ---------------------------------------------------------------------------
__global__ void esq_kernel(const float* __restrict__ E) {
    if (blockIdx.x == 0 && threadIdx.x == 0) g_nflag = 0;
    int k    = blockIdx.x * 8 + (threadIdx.x >> 5);
    int lane = threadIdx.x & 31;
    const float* row = E + (size_t)k * DD;
    float s = 0.f;
#pragma unroll
    for (int d = lane; d < DD; d += 32) { float v = row[d]; s = fmaf(v, v, s); }
#pragma unroll
    for (int o = 16; o; o >>= 1) s += __shfl_xor_sync(0xffffffffu, s, o);
    if (lane == 0) g_esq[k] = s;
}

__global__ void splitE_kernel(const float* __restrict__ E) {
    int i = blockIdx.x * 256 + threadIdx.x;
    float v = E[i];
    __nv_bfloat16 hi = __float2bfloat16(v);
    __nv_bfloat16 lo = __float2bfloat16(v - __bfloat162float(hi));
    g_Ehi[i] = hi; g_Elo[i] = lo;
}

__global__ void splitZ_kernel(const float* __restrict__ z) {
    __shared__ float t[32][33];
    int bx = blockIdx.x, by = blockIdx.y;
    int tx = threadIdx.x, ty = threadIdx.y;
    int n = bx * 32 + tx;
#pragma unroll
    for (int i = 0; i < 4; i++) {
        int d = by * 32 + ty + i * 8;
        t[ty + i * 8][tx] = z[(size_t)d * NTOK + n];
    }
    __syncthreads();
    int d2 = by * 32 + tx;
#pragma unroll
    for (int i = 0; i < 4; i++) {
        int n2 = bx * 32 + ty + i * 8;
        float v = t[tx][ty + i * 8];
        __nv_bfloat16 hi = __float2bfloat16(v);
        __nv_bfloat16 lo = __float2bfloat16(v - __bfloat162float(hi));
        g_zhi[(size_t)n2 * DD + d2] = hi;
        g_zlo[(size_t)n2 * DD + d2] = lo;
    }
}

// ---------------------------------------------------------------------------
__device__ __forceinline__ void mma_bf16(float c[4], const uint32_t a[4], const uint32_t* b) {
    asm volatile(
        "mma.sync.aligned.m16n8k16.row.col.f32.bf16.bf16.f32 "
        "{%0,%1,%2,%3}, {%4,%5,%6,%7}, {%8,%9}, {%0,%1,%2,%3};\n"
        : "+f"(c[0]), "+f"(c[1]), "+f"(c[2]), "+f"(c[3])
        : "r"(a[0]), "r"(a[1]), "r"(a[2]), "r"(a[3]), "r"(b[0]), "r"(b[1]));
}

__device__ __forceinline__ void ldsm4(uint32_t r[4], uint32_t addr) {
    asm volatile("ldmatrix.sync.aligned.m8n8.x4.shared.b16 {%0,%1,%2,%3}, [%4];\n"
        : "=r"(r[0]), "=r"(r[1]), "=r"(r[2]), "=r"(r[3]) : "r"(addr));
}

__device__ __forceinline__ void cp16(uint32_t dst, const void* src) {
    asm volatile("cp.async.cg.shared.global [%0], [%1], 16;\n" :: "r"(dst), "l"(src));
}
__device__ __forceinline__ void cp_commit() { asm volatile("cp.async.commit_group;\n"); }
__device__ __forceinline__ void cp_wait0()  { asm volatile("cp.async.wait_group 0;\n"); }

__device__ __forceinline__ void merge3(float& b1, int& i1, float& b2, float v, int i) {
    if (v < b1) { b2 = b1; b1 = v; i1 = i; }
    else if (v < b2) { b2 = v; }
}
__device__ __forceinline__ void merge3t(float& b1, int& i1, float& b2,
                                        float B1, int I1, float B2) {
    if (B1 < b1) { b2 = fminf(b1, B2); b1 = B1; i1 = I1; }
    else         { b2 = fminf(b2, B1); }
}

__global__ __launch_bounds__(256, 2) void argmin_mma_kernel() {
    extern __shared__ char smem[];
    __nv_bfloat16* As_hi = (__nv_bfloat16*)smem;                 // 64 x 264 (hi)
    __nv_bfloat16* As_lo = As_hi + BM * AS;                      // 64 x 264 (lo)
    __nv_bfloat16* Bs    = As_lo + BM * AS;                      // [buf][hi|lo] 128 x 40
    // final-reduce arrays overlap the A panel (only used after all compute)
    float* sB1 = (float*)smem;                                   // [4][BM]
    int*   sI1 = (int*)(sB1 + 4 * BM);
    float* sB2 = (float*)(sI1 + 4 * BM);

    const int tid  = threadIdx.x;
    const int lane = tid & 31;
    const int wid  = tid >> 5;
    const int warpRow = wid >> 2;     // 2 groups x 32 tokens
    const int warpCol = wid & 3;      // 4 groups x 32 codes
    const int n0 = blockIdx.x * BM;

    const uint32_t bsAddr = (uint32_t)__cvta_generic_to_shared(Bs);

    // prefetch B tile 0 (kc=0, d0=0) into buf 0
    {
#pragma unroll
        for (int it = 0; it < 2; it++) {
            int idx = tid + it * 256;
            int c = idx >> 2, seg = idx & 3;
            uint32_t dst = bsAddr + (uint32_t)(c * BSs + seg * 8) * 2;
            cp16(dst,            g_Ehi + (size_t)c * DD + seg * 8);
            cp16(dst + 2 * BUFE, g_Elo + (size_t)c * DD + seg * 8);
        }
        cp_commit();
    }

    // load the 64-token A panel (full D, hi+lo)
#pragma unroll
    for (int it = 0; it < 8; it++) {
        int idx = tid + it * 256;
        int r = idx >> 5, seg = idx & 31;
        const uint4* sh = (const uint4*)(g_zhi + (size_t)(n0 + r) * DD) + seg;
        const uint4* sl = (const uint4*)(g_zlo + (size_t)(n0 + r) * DD) + seg;
        *(uint4*)(As_hi + r * AS + seg * 8) = *sh;
        *(uint4*)(As_lo + r * AS + seg * 8) = *sl;
    }

    // fragment base addresses (ldmatrix lane-address patterns)
    const uint32_t aHiBase = (uint32_t)__cvta_generic_to_shared(As_hi)
        + (uint32_t)(((warpRow * 32 + (lane & 15)) * AS + (lane >> 4) * 8) * 2);
    const uint32_t aLoBase = aHiBase + (uint32_t)(BM * AS * 2);
    const uint32_t bColOff = (uint32_t)(((warpCol * 32 + (lane >> 4) * 8 + (lane & 7)) * BSs
                                        + ((lane >> 3) & 1) * 8) * 2);

    // persistent per-thread top-2 (4 token rows each)
    float tb1[4], tb2[4]; int ti1[4];
#pragma unroll
    for (int r = 0; r < 4; r++) { tb1[r] = 3.4e38f; tb2[r] = 3.4e38f; ti1[r] = 0; }

    int buf = 0;
    for (int kci = 0; kci < KCB / BN; kci++) {
        const int kc = kci * BN;

        // init acc with -0.5 * e_sq so final score = -2*acc = e_sq - 2*dot
        float acc[2][4][4];
#pragma unroll
        for (int ni = 0; ni < 4; ni++)
#pragma unroll
            for (int e2 = 0; e2 < 2; e2++) {
                float v = -0.5f * __ldg(&g_esq[kc + warpCol * 32 + ni * 8 + (lane & 3) * 2 + e2]);
#pragma unroll
                for (int mi = 0; mi < 2; mi++) {
                    acc[mi][ni][e2]     = v;
                    acc[mi][ni][2 + e2] = v;
                }
            }

        for (int di = 0; di < 8; di++) {
            const int t = kci * 8 + di;
            cp_wait0();
            __syncthreads();
            if (t + 1 < NTILE) {                       // prefetch next tile
                int nkc = ((t + 1) >> 3) * BN;
                int nd0 = ((t + 1) & 7) * BKD;
                uint32_t bb = bsAddr + (uint32_t)((buf ^ 1) * 4 * BUFE);
#pragma unroll
                for (int it = 0; it < 2; it++) {
                    int idx = tid + it * 256;
                    int c = idx >> 2, seg = idx & 3;
                    uint32_t dst = bb + (uint32_t)(c * BSs + seg * 8) * 2;
                    cp16(dst,            g_Ehi + (size_t)(nkc + c) * DD + nd0 + seg * 8);
                    cp16(dst + 2 * BUFE, g_Elo + (size_t)(nkc + c) * DD + nd0 + seg * 8);
                }
                cp_commit();
            }

            const int d0 = di * BKD;
            const uint32_t bHi = bsAddr + (uint32_t)(buf * 4 * BUFE) + bColOff;
            const uint32_t bLo = bHi + 2 * BUFE;
#pragma unroll
            for (int ks = 0; ks < 2; ks++) {
                const uint32_t aOff = (uint32_t)((d0 + ks * 16) * 2);
                uint32_t ah[2][4], al[2][4];
                ldsm4(ah[0], aHiBase + aOff);
                ldsm4(ah[1], aHiBase + aOff + 16 * AS * 2);
                ldsm4(al[0], aLoBase + aOff);
                ldsm4(al[1], aLoBase + aOff + 16 * AS * 2);

                uint32_t bh[8], bl[8];                  // [ni*2 + {b0,b1}]
                const uint32_t kOff = (uint32_t)(ks * 16 * 2);
                ldsm4(bh,     bHi + kOff);
                ldsm4(bh + 4, bHi + kOff + 16 * BSs * 2);
                ldsm4(bl,     bLo + kOff);
                ldsm4(bl + 4, bLo + kOff + 16 * BSs * 2);

#pragma unroll
                for (int mi = 0; mi < 2; mi++)
#pragma unroll
                    for (int ni = 0; ni < 4; ni++) {
                        mma_bf16(acc[mi][ni], ah[mi], bh + ni * 2);   // hi*hi
                        mma_bf16(acc[mi][ni], ah[mi], bl + ni * 2);   // hi*lo
                        mma_bf16(acc[mi][ni], al[mi], bh + ni * 2);   // lo*hi
                    }
            }
            buf ^= 1;
        }

        // register-only epilogue: fold this 128-code chunk into persistent top-2
#pragma unroll
        for (int mi = 0; mi < 2; mi++)
#pragma unroll
            for (int h = 0; h < 2; h++) {
                int r = mi * 2 + h;
#pragma unroll
                for (int ni = 0; ni < 4; ni++)
#pragma unroll
                    for (int e2 = 0; e2 < 2; e2++) {
                        int colL = warpCol * 32 + ni * 8 + (lane & 3) * 2 + e2;
                        float v = -2.f * acc[mi][ni][h * 2 + e2];
                        merge3(tb1[r], ti1[r], tb2[r], v, kc + colL);
                    }
            }
    }

    // cross-thread reduction (once)
#pragma unroll
    for (int off = 1; off <= 2; off <<= 1)
#pragma unroll
        for (int r = 0; r < 4; r++) {
            float B1 = __shfl_xor_sync(0xffffffffu, tb1[r], off);
            int   I1 = __shfl_xor_sync(0xffffffffu, ti1[r], off);
            float B2 = __shfl_xor_sync(0xffffffffu, tb2[r], off);
            merge3t(tb1[r], ti1[r], tb2[r], B1, I1, B2);
        }
    __syncthreads();                    // done reading As/Bs; reuse smem for reduce
    if ((lane & 3) == 0) {
#pragma unroll
        for (int mi = 0; mi < 2; mi++)
#pragma unroll
            for (int h = 0; h < 2; h++) {
                int row = warpRow * 32 + mi * 16 + (lane >> 2) + h * 8;
                int r = mi * 2 + h;
                sB1[warpCol * BM + row] = tb1[r];
                sI1[warpCol * BM + row] = ti1[r];
                sB2[warpCol * BM + row] = tb2[r];
            }
    }
    __syncthreads();
    if (tid < BM) {
        float b1 = 3.4e38f, b2 = 3.4e38f; int i1 = 0;
#pragma unroll
        for (int w = 0; w < 4; w++)
            merge3t(b1, i1, b2, sB1[w * BM + tid], sI1[w * BM + tid], sB2[w * BM + tid]);
        int n = n0 + tid;
        g_idx[n] = i1;
        if (b2 - b1 <= TAU) {
            g_best[n] = ~0ull;
            int p = atomicAdd(&g_nflag, 1);
            g_flag[p] = n;
        }
    }
}

// ---------------------------------------------------------------------------
__device__ __forceinline__ unsigned int ord_f32(float v) {
    unsigned int s = __float_as_uint(v);
    return (s & 0x80000000u) ? ~s : (s | 0x80000000u);
}

__global__ void rescue_kernel(const float* __restrict__ z, const float* __restrict__ E) {
    __shared__ float zc[4][260];
    __shared__ unsigned long long sk[4][64];
    __shared__ int stok[4];
    const int cnt = g_nflag;
    if (cnt == 0) return;
    const int nbat = (cnt + 3) >> 2;
    const int items = nbat * 8;
    const int tid = threadIdx.x;
    const int t  = tid & 3;
    const int c0 = tid >> 2;

    for (int wi = blockIdx.x; wi < items; wi += gridDim.x) {
        int bat = wi >> 3, split = wi & 7;
        __syncthreads();
        int fi = bat * 4 + t; if (fi >= cnt) fi = cnt - 1;
        int n = g_flag[fi];
        if (c0 == 0) stok[t] = n;
        for (int d = c0; d < DD; d += 64) zc[t][d] = z[(size_t)d * NTOK + n];
        __syncthreads();

        unsigned long long key = ~0ull;
#pragma unroll 1
        for (int j = 0; j < 16; j++) {
            int c = split * 1024 + c0 + 64 * j;
            const float4* er = (const float4*)(E + (size_t)c * DD);
            float s = 0.f;
#pragma unroll
            for (int d4 = 0; d4 < DD / 4; d4++) {
                float4 e = er[d4];
                s = fmaf(e.x, zc[t][d4 * 4 + 0], s);
                s = fmaf(e.y, zc[t][d4 * 4 + 1], s);
                s = fmaf(e.z, zc[t][d4 * 4 + 2], s);
                s = fmaf(e.w, zc[t][d4 * 4 + 3], s);
            }
            float dist = fmaf(-2.f, s, g_esq[c]);
            unsigned long long k = ((unsigned long long)ord_f32(dist) << 13) | (unsigned)c;
            key = min(key, k);
        }
        sk[t][c0] = key;
        __syncthreads();
        if (tid < 4) {
            unsigned long long m = sk[tid][0];
            for (int i = 1; i < 64; i++) m = min(m, sk[tid][i]);
            atomicMin(&g_best[stok[tid]], m);
        }
        __syncthreads();
    }
}

__global__ void rescue_fix_kernel() {
    int cnt = g_nflag;
    int i = blockIdx.x * 256 + threadIdx.x;
    if (i < cnt) {
        int n = g_flag[i];
        g_idx[n] = (int)(g_best[n] & 0x1FFFull);
    }
}

// ---------------------------------------------------------------------------
__global__ void gather_kernel(const float* __restrict__ E, float* __restrict__ out) {
    __shared__ float tile[32][DD + 1];
    const int n0   = blockIdx.x * 32;
    const int tid  = threadIdx.x;
    const int warp = tid >> 5, lane = tid & 31;
#pragma unroll
    for (int r = 0; r < 4; r++) {
        int tk = warp * 4 + r;
        int k  = g_idx[n0 + tk];
        const float* row = E + (size_t)k * DD;
#pragma unroll
        for (int d = lane; d < DD; d += 32) tile[tk][d] = row[d];
    }
    __syncthreads();
    for (int idx = tid; idx < 32 * DD; idx += 256) {
        int d  = idx >> 5;
        int nl = idx & 31;
        out[(size_t)d * NTOK + n0 + nl] = tile[nl][d];
    }
}

__global__ void write_idx_kernel(float* __restrict__ out) {
    int n = blockIdx.x * 256 + threadIdx.x;
    out[(size_t)DD * NTOK + n] = (float)g_idx[n];
}

// ---------------------------------------------------------------------------
extern "C" void kernel_launch(void* const* d_in, const int* in_sizes, int n_in,
                              void* d_out, int out_size) {
    const float* z = (const float*)d_in[0];   // (D, N)
    const float* E = (const float*)d_in[1];   // (K, D)
    float* out = (float*)d_out;

    const int SMEM = 2 * BM * AS * 2          // A panel hi+lo
                   + 2 * 2 * BUFE * 2;        // B double buffer hi+lo
    cudaFuncSetAttribute(argmin_mma_kernel,
                         cudaFuncAttributeMaxDynamicSharedMemorySize, SMEM);

    esq_kernel   <<<KCB / 8, 256>>>(E);
    splitE_kernel<<<KCB * DD / 256, 256>>>(E);
    {
        dim3 b(32, 8), g(NTOK / 32, DD / 32);
        splitZ_kernel<<<g, b>>>(z);
    }
    argmin_mma_kernel<<<NTOK / BM, 256, SMEM>>>();
    rescue_kernel<<<256, 256>>>(z, E);
    rescue_fix_kernel<<<NTOK / 256, 256>>>();
    gather_kernel<<<NTOK / 32, 256>>>(E, out);
    if (out_size >= DD * NTOK + NTOK)
        write_idx_kernel<<<NTOK / 256, 256>>>(out);
}

// round 13
// speedup vs baseline: 3.2961x; 1.3610x over previous
#include <cuda_runtime.h>
#include <cuda_fp16.h>
#include <cstdint>

#define DD   256
#define NTOK 32768
#define KCB  8192

#define BM 64           // tokens per block
#define BN 128          // codes per chunk
#define BKD 32          // d per B tile
#define AS  264         // A smem row stride (elems); 528B rows -> conflict-free LDSM
#define BSs 40          // B smem row stride (elems); 80B rows  -> conflict-free LDSM
#define BUFE (BN * BSs) // elems per B buffer (5120, hi only)
#define NTILE ((KCB / BN) * (DD / BKD))   // 512
#define TAU 0.05f

__device__ float   g_esq[KCB];
__device__ int     g_idx[NTOK];
__device__ __half  g_Ehi[KCB * DD];
__device__ __half  g_zhi[(size_t)NTOK * DD];
__device__ __half  g_zlo[(size_t)NTOK * DD];
__device__ int     g_flag[NTOK];
__device__ unsigned long long g_best[NTOK];
__device__ int     g_nflag;

// ---------------------------------------------------------------------------
__global__ void esq_kernel(const float* __restrict__ E) {
    if (blockIdx.x == 0 && threadIdx.x == 0) g_nflag = 0;
    int k    = blockIdx.x * 8 + (threadIdx.x >> 5);
    int lane = threadIdx.x & 31;
    const float* row = E + (size_t)k * DD;
    float s = 0.f;
#pragma unroll
    for (int d = lane; d < DD; d += 32) { float v = row[d]; s = fmaf(v, v, s); }
#pragma unroll
    for (int o = 16; o; o >>= 1) s += __shfl_xor_sync(0xffffffffu, s, o);
    if (lane == 0) g_esq[k] = s;
}

__global__ void splitE_kernel(const float* __restrict__ E) {
    int i = blockIdx.x * 256 + threadIdx.x;
    g_Ehi[i] = __float2half_rn(E[i]);
}

// Transpose z (D,N) -> (N,D); split into fp16 hi/lo (hi+lo ~= fp32 exact)
__global__ void splitZ_kernel(const float* __restrict__ z) {
    __shared__ float t[32][33];
    int bx = blockIdx.x, by = blockIdx.y;
    int tx = threadIdx.x, ty = threadIdx.y;
    int n = bx * 32 + tx;
#pragma unroll
    for (int i = 0; i < 4; i++) {
        int d = by * 32 + ty + i * 8;
        t[ty + i * 8][tx] = z[(size_t)d * NTOK + n];
    }
    __syncthreads();
    int d2 = by * 32 + tx;
#pragma unroll
    for (int i = 0; i < 4; i++) {
        int n2 = bx * 32 + ty + i * 8;
        float v = t[tx][ty + i * 8];
        __half hi = __float2half_rn(v);
        __half lo = __float2half_rn(v - __half2float(hi));
        g_zhi[(size_t)n2 * DD + d2] = hi;
        g_zlo[(size_t)n2 * DD + d2] = lo;
    }
}

// ---------------------------------------------------------------------------
__device__ __forceinline__ void mma_fp16(float c[4], const uint32_t a[4], const uint32_t* b) {
    asm volatile(
        "mma.sync.aligned.m16n8k16.row.col.f32.f16.f16.f32 "
        "{%0,%1,%2,%3}, {%4,%5,%6,%7}, {%8,%9}, {%0,%1,%2,%3};\n"
        : "+f"(c[0]), "+f"(c[1]), "+f"(c[2]), "+f"(c[3])
        : "r"(a[0]), "r"(a[1]), "r"(a[2]), "r"(a[3]), "r"(b[0]), "r"(b[1]));
}

__device__ __forceinline__ void ldsm4(uint32_t r[4], uint32_t addr) {
    asm volatile("ldmatrix.sync.aligned.m8n8.x4.shared.b16 {%0,%1,%2,%3}, [%4];\n"
        : "=r"(r[0]), "=r"(r[1]), "=r"(r[2]), "=r"(r[3]) : "r"(addr));
}

__device__ __forceinline__ void cp16(uint32_t dst, const void* src) {
    asm volatile("cp.async.cg.shared.global [%0], [%1], 16;\n" :: "r"(dst), "l"(src));
}
__device__ __forceinline__ void cp_commit() { asm volatile("cp.async.commit_group;\n"); }
__device__ __forceinline__ void cp_wait0()  { asm volatile("cp.async.wait_group 0;\n"); }

__device__ __forceinline__ void merge3(float& b1, int& i1, float& b2, float v, int i) {
    if (v < b1) { b2 = b1; b1 = v; i1 = i; }
    else if (v < b2) { b2 = v; }
}
__device__ __forceinline__ void merge3t(float& b1, int& i1, float& b2,
                                        float B1, int I1, float B2) {
    if (B1 < b1) { b2 = fminf(b1, B2); b1 = B1; i1 = I1; }
    else         { b2 = fminf(b2, B1); }
}

__global__ __launch_bounds__(256, 2) void argmin_mma_kernel() {
    extern __shared__ char smem[];
    __half* As_hi = (__half*)smem;                 // 64 x 264 (hi)
    __half* As_lo = As_hi + BM * AS;               // 64 x 264 (lo)
    __half* Bs    = As_lo + BM * AS;               // 2 stages x 128 x 40 (hi only)
    // final-reduce arrays overlap the A panel (only used after all compute)
    float* sB1 = (float*)smem;                     // [4][BM]
    int*   sI1 = (int*)(sB1 + 4 * BM);
    float* sB2 = (float*)(sI1 + 4 * BM);

    const int tid  = threadIdx.x;
    const int lane = tid & 31;
    const int wid  = tid >> 5;
    const int warpRow = wid >> 2;     // 2 groups x 32 tokens
    const int warpCol = wid & 3;      // 4 groups x 32 codes
    const int n0 = blockIdx.x * BM;

    const uint32_t bsAddr = (uint32_t)__cvta_generic_to_shared(Bs);

    // prefetch B tile 0 (kc=0, d0=0) into buf 0  (2 x 16B per thread)
    {
#pragma unroll
        for (int it = 0; it < 2; it++) {
            int idx = tid + it * 256;
            int c = idx >> 2, seg = idx & 3;
            cp16(bsAddr + (uint32_t)(c * BSs + seg * 8) * 2,
                 g_Ehi + (size_t)c * DD + seg * 8);
        }
        cp_commit();
    }

    // load the 64-token A panel (full D, hi+lo)
#pragma unroll
    for (int it = 0; it < 8; it++) {
        int idx = tid + it * 256;
        int r = idx >> 5, seg = idx & 31;
        const uint4* sh = (const uint4*)(g_zhi + (size_t)(n0 + r) * DD) + seg;
        const uint4* sl = (const uint4*)(g_zlo + (size_t)(n0 + r) * DD) + seg;
        *(uint4*)(As_hi + r * AS + seg * 8) = *sh;
        *(uint4*)(As_lo + r * AS + seg * 8) = *sl;
    }

    // fragment base addresses (ldmatrix lane-address patterns)
    const uint32_t aHiBase = (uint32_t)__cvta_generic_to_shared(As_hi)
        + (uint32_t)(((warpRow * 32 + (lane & 15)) * AS + (lane >> 4) * 8) * 2);
    const uint32_t aLoBase = aHiBase + (uint32_t)(BM * AS * 2);
    const uint32_t bColOff = (uint32_t)(((warpCol * 32 + (lane >> 4) * 8 + (lane & 7)) * BSs
                                        + ((lane >> 3) & 1) * 8) * 2);

    // persistent per-thread top-2 (4 token rows each)
    float tb1[4], tb2[4]; int ti1[4];
#pragma unroll
    for (int r = 0; r < 4; r++) { tb1[r] = 3.4e38f; tb2[r] = 3.4e38f; ti1[r] = 0; }

    int buf = 0;
    for (int kci = 0; kci < KCB / BN; kci++) {
        const int kc = kci * BN;

        // init acc with -0.5 * e_sq so final score = -2*acc = e_sq - 2*dot
        float acc[2][4][4];
#pragma unroll
        for (int ni = 0; ni < 4; ni++)
#pragma unroll
            for (int e2 = 0; e2 < 2; e2++) {
                float v = -0.5f * __ldg(&g_esq[kc + warpCol * 32 + ni * 8 + (lane & 3) * 2 + e2]);
#pragma unroll
                for (int mi = 0; mi < 2; mi++) {
                    acc[mi][ni][e2]     = v;
                    acc[mi][ni][2 + e2] = v;
                }
            }

        for (int di = 0; di < 8; di++) {
            const int t = kci * 8 + di;
            cp_wait0();
            __syncthreads();
            if (t + 1 < NTILE) {                       // prefetch next tile
                int nkc = ((t + 1) >> 3) * BN;
                int nd0 = ((t + 1) & 7) * BKD;
                uint32_t bb = bsAddr + (uint32_t)((buf ^ 1) * 2 * BUFE);
#pragma unroll
                for (int it = 0; it < 2; it++) {
                    int idx = tid + it * 256;
                    int c = idx >> 2, seg = idx & 3;
                    cp16(bb + (uint32_t)(c * BSs + seg * 8) * 2,
                         g_Ehi + (size_t)(nkc + c) * DD + nd0 + seg * 8);
                }
                cp_commit();
            }

            const int d0 = di * BKD;
            const uint32_t bHi = bsAddr + (uint32_t)(buf * 2 * BUFE) + bColOff;
#pragma unroll
            for (int ks = 0; ks < 2; ks++) {
                const uint32_t aOff = (uint32_t)((d0 + ks * 16) * 2);
                uint32_t ah[2][4], al[2][4];
                ldsm4(ah[0], aHiBase + aOff);
                ldsm4(ah[1], aHiBase + aOff + 16 * AS * 2);
                ldsm4(al[0], aLoBase + aOff);
                ldsm4(al[1], aLoBase + aOff + 16 * AS * 2);

                uint32_t bh[8];                         // [ni*2 + {b0,b1}]
                const uint32_t kOff = (uint32_t)(ks * 16 * 2);
                ldsm4(bh,     bHi + kOff);
                ldsm4(bh + 4, bHi + kOff + 16 * BSs * 2);

#pragma unroll
                for (int mi = 0; mi < 2; mi++)
#pragma unroll
                    for (int ni = 0; ni < 4; ni++) {
                        mma_fp16(acc[mi][ni], ah[mi], bh + ni * 2);   // z_hi * e_hi
                        mma_fp16(acc[mi][ni], al[mi], bh + ni * 2);   // z_lo * e_hi
                    }
            }
            buf ^= 1;
        }

        // register-only epilogue: fold this 128-code chunk into persistent top-2
#pragma unroll
        for (int mi = 0; mi < 2; mi++)
#pragma unroll
            for (int h = 0; h < 2; h++) {
                int r = mi * 2 + h;
#pragma unroll
                for (int ni = 0; ni < 4; ni++)
#pragma unroll
                    for (int e2 = 0; e2 < 2; e2++) {
                        int colL = warpCol * 32 + ni * 8 + (lane & 3) * 2 + e2;
                        float v = -2.f * acc[mi][ni][h * 2 + e2];
                        merge3(tb1[r], ti1[r], tb2[r], v, kc + colL);
                    }
            }
    }

    // cross-thread reduction (once)
#pragma unroll
    for (int off = 1; off <= 2; off <<= 1)
#pragma unroll
        for (int r = 0; r < 4; r++) {
            float B1 = __shfl_xor_sync(0xffffffffu, tb1[r], off);
            int   I1 = __shfl_xor_sync(0xffffffffu, ti1[r], off);
            float B2 = __shfl_xor_sync(0xffffffffu, tb2[r], off);
            merge3t(tb1[r], ti1[r], tb2[r], B1, I1, B2);
        }
    __syncthreads();                    // done reading As/Bs; reuse smem for reduce
    if ((lane & 3) == 0) {
#pragma unroll
        for (int mi = 0; mi < 2; mi++)
#pragma unroll
            for (int h = 0; h < 2; h++) {
                int row = warpRow * 32 + mi * 16 + (lane >> 2) + h * 8;
                int r = mi * 2 + h;
                sB1[warpCol * BM + row] = tb1[r];
                sI1[warpCol * BM + row] = ti1[r];
                sB2[warpCol * BM + row] = tb2[r];
            }
    }
    __syncthreads();
    if (tid < BM) {
        float b1 = 3.4e38f, b2 = 3.4e38f; int i1 = 0;
#pragma unroll
        for (int w = 0; w < 4; w++)
            merge3t(b1, i1, b2, sB1[w * BM + tid], sI1[w * BM + tid], sB2[w * BM + tid]);
        int n = n0 + tid;
        g_idx[n] = i1;
        if (b2 - b1 <= TAU) {
            g_best[n] = ~0ull;
            int p = atomicAdd(&g_nflag, 1);
            g_flag[p] = n;
        }
    }
}

// ---------------------------------------------------------------------------
__device__ __forceinline__ unsigned int ord_f32(float v) {
    unsigned int s = __float_as_uint(v);
    return (s & 0x80000000u) ? ~s : (s | 0x80000000u);
}

// Exact fp32 re-scoring of flagged tokens over all K codes.
__global__ void rescue_kernel(const float* __restrict__ z, const float* __restrict__ E) {
    __shared__ float zc[4][260];
    __shared__ unsigned long long sk[4][64];
    __shared__ int stok[4];
    const int cnt = g_nflag;
    if (cnt == 0) return;
    const int nbat = (cnt + 3) >> 2;
    const int items = nbat * 8;
    const int tid = threadIdx.x;
    const int t  = tid & 3;
    const int c0 = tid >> 2;

    for (int wi = blockIdx.x; wi < items; wi += gridDim.x) {
        int bat = wi >> 3, split = wi & 7;
        __syncthreads();
        int fi = bat * 4 + t; if (fi >= cnt) fi = cnt - 1;
        int n = g_flag[fi];
        if (c0 == 0) stok[t] = n;
        for (int d = c0; d < DD; d += 64) zc[t][d] = z[(size_t)d * NTOK + n];
        __syncthreads();

        unsigned long long key = ~0ull;
#pragma unroll 1
        for (int j = 0; j < 16; j++) {
            int c = split * 1024 + c0 + 64 * j;
            const float4* er = (const float4*)(E + (size_t)c * DD);
            float s = 0.f;
#pragma unroll
            for (int d4 = 0; d4 < DD / 4; d4++) {
                float4 e = er[d4];
                s = fmaf(e.x, zc[t][d4 * 4 + 0], s);
                s = fmaf(e.y, zc[t][d4 * 4 + 1], s);
                s = fmaf(e.z, zc[t][d4 * 4 + 2], s);
                s = fmaf(e.w, zc[t][d4 * 4 + 3], s);
            }
            float dist = fmaf(-2.f, s, g_esq[c]);
            unsigned long long k = ((unsigned long long)ord_f32(dist) << 13) | (unsigned)c;
            key = min(key, k);
        }
        sk[t][c0] = key;
        __syncthreads();
        if (tid < 4) {
            unsigned long long m = sk[tid][0];
            for (int i = 1; i < 64; i++) m = min(m, sk[tid][i]);
            atomicMin(&g_best[stok[tid]], m);
        }
        __syncthreads();
    }
}

__global__ void rescue_fix_kernel() {
    int cnt = g_nflag;
    int i = blockIdx.x * 256 + threadIdx.x;
    if (i < cnt) {
        int n = g_flag[i];
        g_idx[n] = (int)(g_best[n] & 0x1FFFull);
    }
}

// ---------------------------------------------------------------------------
__global__ void gather_kernel(const float* __restrict__ E, float* __restrict__ out) {
    __shared__ float tile[32][DD + 1];
    const int n0   = blockIdx.x * 32;
    const int tid  = threadIdx.x;
    const int warp = tid >> 5, lane = tid & 31;
#pragma unroll
    for (int r = 0; r < 4; r++) {
        int tk = warp * 4 + r;
        int k  = g_idx[n0 + tk];
        const float* row = E + (size_t)k * DD;
#pragma unroll
        for (int d = lane; d < DD; d += 32) tile[tk][d] = row[d];
    }
    __syncthreads();
    for (int idx = tid; idx < 32 * DD; idx += 256) {
        int d  = idx >> 5;
        int nl = idx & 31;
        out[(size_t)d * NTOK + n0 + nl] = tile[nl][d];
    }
}

__global__ void write_idx_kernel(float* __restrict__ out) {
    int n = blockIdx.x * 256 + threadIdx.x;
    out[(size_t)DD * NTOK + n] = (float)g_idx[n];
}

// ---------------------------------------------------------------------------
extern "C" void kernel_launch(void* const* d_in, const int* in_sizes, int n_in,
                              void* d_out, int out_size) {
    const float* z = (const float*)d_in[0];   // (D, N)
    const float* E = (const float*)d_in[1];   // (K, D)
    float* out = (float*)d_out;

    const int SMEM = 2 * BM * AS * 2          // A panel hi+lo (fp16)
                   + 2 * BUFE * 2;            // B double buffer (hi only)
    cudaFuncSetAttribute(argmin_mma_kernel,
                         cudaFuncAttributeMaxDynamicSharedMemorySize, SMEM);

    esq_kernel   <<<KCB / 8, 256>>>(E);
    splitE_kernel<<<KCB * DD / 256, 256>>>(E);
    {
        dim3 b(32, 8), g(NTOK / 32, DD / 32);
        splitZ_kernel<<<g, b>>>(z);
    }
    argmin_mma_kernel<<<NTOK / BM, 256, SMEM>>>();
    rescue_kernel<<<256, 256>>>(z, E);
    rescue_fix_kernel<<<NTOK / 256, 256>>>();
    gather_kernel<<<NTOK / 32, 256>>>(E, out);
    if (out_size >= DD * NTOK + NTOK)
        write_idx_kernel<<<NTOK / 256, 256>>>(out);
}

// round 17
// speedup vs baseline: 4.1024x; 1.2446x over previous
#include <cuda_runtime.h>
#include <cuda_fp16.h>
#include <cstdint>

#define DD   256
#define NTOK 32768
#define KCB  8192

#define BM 128          // tokens per block
#define BN 128          // codes per chunk
#define BKD 32          // d per B tile
#define AS  264         // A smem row stride (elems); 528B rows -> conflict-free LDSM
#define BSs 40          // B smem row stride (elems); 80B rows  -> conflict-free LDSM
#define BUFE (BN * BSs) // elems per B buffer (5120)
#define NTILE ((KCB / BN) * (DD / BKD))   // 512
#define TAU 0.12f

__device__ float   g_esq[KCB];
__device__ int     g_idx[NTOK];
__device__ __half  g_Ehi[KCB * DD];
__device__ __half  g_zhi[(size_t)NTOK * DD];
__device__ int     g_flag[NTOK];
__device__ unsigned long long g_best[NTOK];
__device__ int     g_nflag;

// ---------------------------------------------------------------------------
__global__ void esq_kernel(const float* __restrict__ E) {
    if (blockIdx.x == 0 && threadIdx.x == 0) g_nflag = 0;
    int k    = blockIdx.x * 8 + (threadIdx.x >> 5);
    int lane = threadIdx.x & 31;
    const float* row = E + (size_t)k * DD;
    float s = 0.f;
#pragma unroll
    for (int d = lane; d < DD; d += 32) { float v = row[d]; s = fmaf(v, v, s); }
#pragma unroll
    for (int o = 16; o; o >>= 1) s += __shfl_xor_sync(0xffffffffu, s, o);
    if (lane == 0) g_esq[k] = s;
}

__global__ void splitE_kernel(const float* __restrict__ E) {
    int i = blockIdx.x * 256 + threadIdx.x;
    g_Ehi[i] = __float2half_rn(E[i]);
}

// Transpose z (D,N) -> (N,D) fp16
__global__ void splitZ_kernel(const float* __restrict__ z) {
    __shared__ float t[32][33];
    int bx = blockIdx.x, by = blockIdx.y;
    int tx = threadIdx.x, ty = threadIdx.y;
    int n = bx * 32 + tx;
#pragma unroll
    for (int i = 0; i < 4; i++) {
        int d = by * 32 + ty + i * 8;
        t[ty + i * 8][tx] = z[(size_t)d * NTOK + n];
    }
    __syncthreads();
    int d2 = by * 32 + tx;
#pragma unroll
    for (int i = 0; i < 4; i++) {
        int n2 = bx * 32 + ty + i * 8;
        g_zhi[(size_t)n2 * DD + d2] = __float2half_rn(t[tx][ty + i * 8]);
    }
}

// ---------------------------------------------------------------------------
__device__ __forceinline__ void mma_fp16(float c[4], const uint32_t a[4], const uint32_t* b) {
    asm volatile(
        "mma.sync.aligned.m16n8k16.row.col.f32.f16.f16.f32 "
        "{%0,%1,%2,%3}, {%4,%5,%6,%7}, {%8,%9}, {%0,%1,%2,%3};\n"
        : "+f"(c[0]), "+f"(c[1]), "+f"(c[2]), "+f"(c[3])
        : "r"(a[0]), "r"(a[1]), "r"(a[2]), "r"(a[3]), "r"(b[0]), "r"(b[1]));
}

__device__ __forceinline__ void ldsm4(uint32_t r[4], uint32_t addr) {
    asm volatile("ldmatrix.sync.aligned.m8n8.x4.shared.b16 {%0,%1,%2,%3}, [%4];\n"
        : "=r"(r[0]), "=r"(r[1]), "=r"(r[2]), "=r"(r[3]) : "r"(addr));
}

__device__ __forceinline__ void cp16(uint32_t dst, const void* src) {
    asm volatile("cp.async.cg.shared.global [%0], [%1], 16;\n" :: "r"(dst), "l"(src));
}
__device__ __forceinline__ void cp_commit() { asm volatile("cp.async.commit_group;\n"); }
__device__ __forceinline__ void cp_wait0()  { asm volatile("cp.async.wait_group 0;\n"); }

__device__ __forceinline__ void merge3(float& b1, int& i1, float& b2, float v, int i) {
    if (v < b1) { b2 = b1; b1 = v; i1 = i; }
    else if (v < b2) { b2 = v; }
}
__device__ __forceinline__ void merge3t(float& b1, int& i1, float& b2,
                                        float B1, int I1, float B2) {
    if (B1 < b1) { b2 = fminf(b1, B2); b1 = B1; i1 = I1; }
    else         { b2 = fminf(b2, B1); }
}

__global__ __launch_bounds__(256, 2) void argmin_mma_kernel() {
    extern __shared__ char smem[];
    __half* As = (__half*)smem;                    // 128 x 264 fp16
    __half* Bs = As + BM * AS;                     // 2 stages x 128 x 40
    // final-reduce arrays overlap the A panel (only used after all compute)
    float* sB1 = (float*)smem;                     // [2][BM]
    int*   sI1 = (int*)(sB1 + 2 * BM);
    float* sB2 = (float*)(sI1 + 2 * BM);

    const int tid  = threadIdx.x;
    const int lane = tid & 31;
    const int wid  = tid >> 5;
    const int warpRow = wid >> 1;     // 4 groups x 32 tokens
    const int warpCol = wid & 1;      // 2 groups x 64 codes
    const int n0 = blockIdx.x * BM;

    const uint32_t bsAddr = (uint32_t)__cvta_generic_to_shared(Bs);

    // prefetch B tile 0 (kc=0, d0=0) into buf 0
    {
#pragma unroll
        for (int it = 0; it < 2; it++) {
            int idx = tid + it * 256;
            int c = idx >> 2, seg = idx & 3;
            cp16(bsAddr + (uint32_t)(c * BSs + seg * 8) * 2,
                 g_Ehi + (size_t)c * DD + seg * 8);
        }
        cp_commit();
    }

    // load the 128-token A panel (full D)
#pragma unroll
    for (int it = 0; it < 16; it++) {
        int idx = tid + it * 256;
        int r = idx >> 5, seg = idx & 31;
        *(uint4*)(As + r * AS + seg * 8) =
            *((const uint4*)(g_zhi + (size_t)(n0 + r) * DD) + seg);
    }

    // fragment base addresses (ldmatrix lane-address patterns)
    const uint32_t aBase = (uint32_t)__cvta_generic_to_shared(As)
        + (uint32_t)(((warpRow * 32 + (lane & 15)) * AS + (lane >> 4) * 8) * 2);
    const uint32_t bColOff = (uint32_t)(((warpCol * 64 + (lane >> 4) * 8 + (lane & 7)) * BSs
                                        + ((lane >> 3) & 1) * 8) * 2);

    // persistent per-thread top-2 (4 token rows each)
    float tb1[4], tb2[4]; int ti1[4];
#pragma unroll
    for (int r = 0; r < 4; r++) { tb1[r] = 3.4e38f; tb2[r] = 3.4e38f; ti1[r] = 0; }

    int buf = 0;
    for (int kci = 0; kci < KCB / BN; kci++) {
        const int kc = kci * BN;

        // init acc with -0.5 * e_sq so final score = -2*acc = e_sq - 2*dot
        float acc[2][8][4];
#pragma unroll
        for (int ni = 0; ni < 8; ni++)
#pragma unroll
            for (int e2 = 0; e2 < 2; e2++) {
                float v = -0.5f * __ldg(&g_esq[kc + warpCol * 64 + ni * 8 + (lane & 3) * 2 + e2]);
#pragma unroll
                for (int mi = 0; mi < 2; mi++) {
                    acc[mi][ni][e2]     = v;
                    acc[mi][ni][2 + e2] = v;
                }
            }

        for (int di = 0; di < 8; di++) {
            const int t = kci * 8 + di;
            cp_wait0();
            __syncthreads();
            if (t + 1 < NTILE) {                       // prefetch next tile
                int nkc = ((t + 1) >> 3) * BN;
                int nd0 = ((t + 1) & 7) * BKD;
                uint32_t bb = bsAddr + (uint32_t)((buf ^ 1) * 2 * BUFE);
#pragma unroll
                for (int it = 0; it < 2; it++) {
                    int idx = tid + it * 256;
                    int c = idx >> 2, seg = idx & 3;
                    cp16(bb + (uint32_t)(c * BSs + seg * 8) * 2,
                         g_Ehi + (size_t)(nkc + c) * DD + nd0 + seg * 8);
                }
                cp_commit();
            }

            const int d0 = di * BKD;
            const uint32_t bHi = bsAddr + (uint32_t)(buf * 2 * BUFE) + bColOff;
#pragma unroll
            for (int ks = 0; ks < 2; ks++) {
                const uint32_t aOff = (uint32_t)((d0 + ks * 16) * 2);
                uint32_t ah[2][4];
                ldsm4(ah[0], aBase + aOff);
                ldsm4(ah[1], aBase + aOff + 16 * AS * 2);

                uint32_t bh[16];                        // [ni*2 + {b0,b1}]
                const uint32_t kOff = (uint32_t)(ks * 16 * 2);
                ldsm4(bh,      bHi + kOff);
                ldsm4(bh + 4,  bHi + kOff + 16 * BSs * 2);
                ldsm4(bh + 8,  bHi + kOff + 32 * BSs * 2);
                ldsm4(bh + 12, bHi + kOff + 48 * BSs * 2);

#pragma unroll
                for (int mi = 0; mi < 2; mi++)
#pragma unroll
                    for (int ni = 0; ni < 8; ni++)
                        mma_fp16(acc[mi][ni], ah[mi], bh + ni * 2);
            }
            buf ^= 1;
        }

        // register-only epilogue: fold this 128-code chunk into persistent top-2
#pragma unroll
        for (int mi = 0; mi < 2; mi++)
#pragma unroll
            for (int h = 0; h < 2; h++) {
                int r = mi * 2 + h;
#pragma unroll
                for (int ni = 0; ni < 8; ni++)
#pragma unroll
                    for (int e2 = 0; e2 < 2; e2++) {
                        int colL = warpCol * 64 + ni * 8 + (lane & 3) * 2 + e2;
                        float v = -2.f * acc[mi][ni][h * 2 + e2];
                        merge3(tb1[r], ti1[r], tb2[r], v, kc + colL);
                    }
            }
    }

    // cross-thread reduction (once)
#pragma unroll
    for (int off = 1; off <= 2; off <<= 1)
#pragma unroll
        for (int r = 0; r < 4; r++) {
            float B1 = __shfl_xor_sync(0xffffffffu, tb1[r], off);
            int   I1 = __shfl_xor_sync(0xffffffffu, ti1[r], off);
            float B2 = __shfl_xor_sync(0xffffffffu, tb2[r], off);
            merge3t(tb1[r], ti1[r], tb2[r], B1, I1, B2);
        }
    __syncthreads();                    // done reading As/Bs; reuse smem for reduce
    if ((lane & 3) == 0) {
#pragma unroll
        for (int mi = 0; mi < 2; mi++)
#pragma unroll
            for (int h = 0; h < 2; h++) {
                int row = warpRow * 32 + mi * 16 + (lane >> 2) + h * 8;
                int r = mi * 2 + h;
                sB1[warpCol * BM + row] = tb1[r];
                sI1[warpCol * BM + row] = ti1[r];
                sB2[warpCol * BM + row] = tb2[r];
            }
    }
    __syncthreads();
    if (tid < BM) {
        float b1 = 3.4e38f, b2 = 3.4e38f; int i1 = 0;
#pragma unroll
        for (int w = 0; w < 2; w++)
            merge3t(b1, i1, b2, sB1[w * BM + tid], sI1[w * BM + tid], sB2[w * BM + tid]);
        int n = n0 + tid;
        g_idx[n] = i1;
        if (b2 - b1 <= TAU) {
            g_best[n] = ~0ull;
            int p = atomicAdd(&g_nflag, 1);
            g_flag[p] = n;
        }
    }
}

// ---------------------------------------------------------------------------
__device__ __forceinline__ unsigned int ord_f32(float v) {
    unsigned int s = __float_as_uint(v);
    return (s & 0x80000000u) ? ~s : (s | 0x80000000u);
}

// Exact fp32 re-scoring of flagged tokens over all K codes.
__global__ void rescue_kernel(const float* __restrict__ z, const float* __restrict__ E) {
    __shared__ float zc[4][260];
    __shared__ unsigned long long sk[4][64];
    __shared__ int stok[4];
    const int cnt = g_nflag;
    if (cnt == 0) return;
    const int nbat = (cnt + 3) >> 2;
    const int items = nbat * 8;
    const int tid = threadIdx.x;
    const int t  = tid & 3;
    const int c0 = tid >> 2;

    for (int wi = blockIdx.x; wi < items; wi += gridDim.x) {
        int bat = wi >> 3, split = wi & 7;
        __syncthreads();
        int fi = bat * 4 + t; if (fi >= cnt) fi = cnt - 1;
        int n = g_flag[fi];
        if (c0 == 0) stok[t] = n;
        for (int d = c0; d < DD; d += 64) zc[t][d] = z[(size_t)d * NTOK + n];
        __syncthreads();

        unsigned long long key = ~0ull;
#pragma unroll 1
        for (int j = 0; j < 16; j++) {
            int c = split * 1024 + c0 + 64 * j;
            const float4* er = (const float4*)(E + (size_t)c * DD);
            float s = 0.f;
#pragma unroll
            for (int d4 = 0; d4 < DD / 4; d4++) {
                float4 e = er[d4];
                s = fmaf(e.x, zc[t][d4 * 4 + 0], s);
                s = fmaf(e.y, zc[t][d4 * 4 + 1], s);
                s = fmaf(e.z, zc[t][d4 * 4 + 2], s);
                s = fmaf(e.w, zc[t][d4 * 4 + 3], s);
            }
            float dist = fmaf(-2.f, s, g_esq[c]);
            unsigned long long k = ((unsigned long long)ord_f32(dist) << 13) | (unsigned)c;
            key = min(key, k);
        }
        sk[t][c0] = key;
        __syncthreads();
        if (tid < 4) {
            unsigned long long m = sk[tid][0];
            for (int i = 1; i < 64; i++) m = min(m, sk[tid][i]);
            atomicMin(&g_best[stok[tid]], m);
        }
        __syncthreads();
    }
}

__global__ void rescue_fix_kernel() {
    int cnt = g_nflag;
    int i = blockIdx.x * 256 + threadIdx.x;
    if (i < cnt) {
        int n = g_flag[i];
        g_idx[n] = (int)(g_best[n] & 0x1FFFull);
    }
}

// ---------------------------------------------------------------------------
__global__ void gather_kernel(const float* __restrict__ E, float* __restrict__ out) {
    __shared__ float tile[32][DD + 1];
    const int n0   = blockIdx.x * 32;
    const int tid  = threadIdx.x;
    const int warp = tid >> 5, lane = tid & 31;
#pragma unroll
    for (int r = 0; r < 4; r++) {
        int tk = warp * 4 + r;
        int k  = g_idx[n0 + tk];
        const float* row = E + (size_t)k * DD;
#pragma unroll
        for (int d = lane; d < DD; d += 32) tile[tk][d] = row[d];
    }
    __syncthreads();
    for (int idx = tid; idx < 32 * DD; idx += 256) {
        int d  = idx >> 5;
        int nl = idx & 31;
        out[(size_t)d * NTOK + n0 + nl] = tile[nl][d];
    }
}

__global__ void write_idx_kernel(float* __restrict__ out) {
    int n = blockIdx.x * 256 + threadIdx.x;
    out[(size_t)DD * NTOK + n] = (float)g_idx[n];
}

// ---------------------------------------------------------------------------
extern "C" void kernel_launch(void* const* d_in, const int* in_sizes, int n_in,
                              void* d_out, int out_size) {
    const float* z = (const float*)d_in[0];   // (D, N)
    const float* E = (const float*)d_in[1];   // (K, D)
    float* out = (float*)d_out;

    const int SMEM = BM * AS * 2              // A panel fp16
                   + 2 * BUFE * 2;            // B double buffer
    cudaFuncSetAttribute(argmin_mma_kernel,
                         cudaFuncAttributeMaxDynamicSharedMemorySize, SMEM);

    esq_kernel   <<<KCB / 8, 256>>>(E);
    splitE_kernel<<<KCB * DD / 256, 256>>>(E);
    {
        dim3 b(32, 8), g(NTOK / 32, DD / 32);
        splitZ_kernel<<<g, b>>>(z);
    }
    argmin_mma_kernel<<<NTOK / BM, 256, SMEM>>>();
    rescue_kernel<<<256, 256>>>(z, E);
    rescue_fix_kernel<<<NTOK / 256, 256>>>();
    gather_kernel<<<NTOK / 32, 256>>>(E, out);
    if (out_size >= DD * NTOK + NTOK)
        write_idx_kernel<<<NTOK / 256, 256>>>(out);
}